// round 9
// baseline (speedup 1.0000x reference)
#include <cuda_runtime.h>
#include <cuda_bf16.h>

#define BATCH 4
#define NP    8192
#define NQ    2048
#define CF    64
#define CT    64
#define KS    32
#define R2    0.04f
#define OUTC  (3 + CF)        // 67 channels in grouped_features
#define QPB   64              // queries per ball-query block

__device__ int g_idx[BATCH * NQ * KS];      // ball-query result (padded)

// Ball query: whole batch cloud resident in 96KB dynamic smem (SoA), loaded
// directly from [B,Np,3]. 1024 threads; each warp scans 2 queries from smem
// with per-warp early exit. Writes g_idx + the 3 centered coord channels.
__global__ __launch_bounds__(1024) void qg_ballquery_kernel(
    const float* __restrict__ coords,
    const float* __restrict__ queries,
    float* __restrict__ out)
{
    extern __shared__ float sxyz[];                  // sx[NP] | sy[NP] | sz[NP]
    float* sx = sxyz;
    __shared__ int slots_s[32][KS];

    int tid  = threadIdx.x;
    int lane = tid & 31;
    int w    = tid >> 5;
    int b    = blockIdx.x >> 5;                      // 32 blocks per batch
    int blk  = blockIdx.x & 31;

    // Load whole cloud once: coalesced reads of the flat [Np*3] array,
    // scatter to SoA smem (d*NP + p).
    const float* cb = coords + (size_t)b * NP * 3;
    #pragma unroll
    for (int j = 0; j < (NP * 3) / 1024; ++j) {
        int i = tid + j * 1024;
        float v = cb[i];
        int p = i / 3, d = i - 3 * p;
        sxyz[d * NP + p] = v;
    }
    __syncthreads();

    float* sy = sxyz + NP;
    float* sz = sxyz + 2 * NP;
    int* slots = slots_s[w];
    unsigned lt = (1u << lane) - 1u;
    const size_t stride = (size_t)NQ * KS;

    #pragma unroll
    for (int j = 0; j < 2; ++j) {
        int q = blk * QPB + w + 32 * j;
        int g = b * NQ + q;
        const float* qp = queries + (size_t)g * 3;
        float qx = qp[0], qy = qp[1], qz = qp[2];

        int count = 0;
        for (int base = 0; base < NP; base += 64) {
            int i0 = base + lane, i1 = base + 32 + lane;
            float x0 = sx[i0], y0 = sy[i0], z0 = sz[i0];
            float x1 = sx[i1], y1 = sy[i1], z1 = sz[i1];
            // Match XLA rounding exactly: no FMA contraction.
            float dx0 = __fadd_rn(qx, -x0), dy0 = __fadd_rn(qy, -y0), dz0 = __fadd_rn(qz, -z0);
            float d20 = __fadd_rn(__fadd_rn(__fmul_rn(dx0, dx0), __fmul_rn(dy0, dy0)),
                                  __fmul_rn(dz0, dz0));
            float dx1 = __fadd_rn(qx, -x1), dy1 = __fadd_rn(qy, -y1), dz1 = __fadd_rn(qz, -z1);
            float d21 = __fadd_rn(__fadd_rn(__fmul_rn(dx1, dx1), __fmul_rn(dy1, dy1)),
                                  __fmul_rn(dz1, dz1));
            bool in0 = d20 < R2;
            bool in1 = d21 < R2;
            unsigned m0 = __ballot_sync(0xffffffffu, in0);
            unsigned m1 = __ballot_sync(0xffffffffu, in1);
            if (in0) {
                int s = count + __popc(m0 & lt);
                if (s < KS) slots[s] = i0;
            }
            int c1 = count + __popc(m0);
            if (in1) {
                int s = c1 + __popc(m1 & lt);
                if (s < KS) slots[s] = i1;
            }
            count = c1 + __popc(m1);
            if (count >= KS) break;
        }
        __syncwarp();

        int cnt   = count < KS ? count : KS;
        int first = (count > 0) ? slots[0] : 0;
        int my    = (lane < cnt) ? slots[lane] : first;
        g_idx[(size_t)g * KS + lane] = my;

        // coord channels 0..2 (centered)
        size_t ob0 = (size_t)b * OUTC * stride + (size_t)q * KS + lane;
        out[ob0]              = sx[my] - qx;
        out[ob0 + stride]     = sy[my] - qy;
        out[ob0 + 2 * stride] = sz[my] - qz;
        __syncwarp();
    }
}

// Gather: one block per (batch, channel plane). 512 blocks total.
// Channel row (32KB) lives in smem; idx streamed coalesced (int4, L2-resident);
// random LDS lookups; fully coalesced STG.128 output.
__global__ __launch_bounds__(256) void qg_gather_kernel(
    const float* __restrict__ feats,
    const float* __restrict__ temb,
    float* __restrict__ out)
{
    __shared__ float row[NP];    // 32KB

    int tid = threadIdx.x;
    int bc  = blockIdx.x;        // 0..511
    int b   = bc >> 7;
    int c   = bc & 127;          // 0..63 feat, 64..127 temb
    int which = c >> 6;
    int ch  = c & 63;

    const float* src = (which ? temb : feats) + ((size_t)b * 64 + ch) * NP;
    // Load channel row into smem (coalesced float4).
    #pragma unroll
    for (int j = 0; j < NP / (256 * 4); ++j) {
        float4 v = *(const float4*)(src + (tid + j * 256) * 4);
        *(float4*)(&row[(tid + j * 256) * 4]) = v;
    }
    __syncthreads();

    const size_t stride = (size_t)NQ * KS;
    size_t ob;                   // base of this output channel plane
    if (which == 0)
        ob = (size_t)b * OUTC * stride + (size_t)(3 + ch) * stride;
    else
        ob = (size_t)BATCH * OUTC * stride + (size_t)b * CT * stride + (size_t)ch * stride;

    const int4* idx4 = (const int4*)(g_idx + (size_t)b * NQ * KS);

    // 64K elements = 16K int4 groups; 256 threads -> 64 iterations.
    #pragma unroll 4
    for (int it = 0; it < (NQ * KS / 4) / 256; ++it) {
        int e = it * 256 + tid;            // group id: q = e>>3, kquad = e&7
        int4 iv = idx4[e];
        float4 v = make_float4(row[iv.x], row[iv.y], row[iv.z], row[iv.w]);
        *(float4*)(out + ob + (size_t)e * 4) = v;
    }
}

extern "C" void kernel_launch(void* const* d_in, const int* in_sizes, int n_in,
                              void* d_out, int out_size) {
    const float* coords  = (const float*)d_in[0];  // [B,Np,3]
    const float* feats   = (const float*)d_in[1];  // [B,C,Np]
    const float* temb    = (const float*)d_in[2];  // [B,Ct,Np]
    const float* queries = (const float*)d_in[3];  // [B,Nq,3]
    float* out = (float*)d_out;

    const int dyn_smem = 3 * NP * (int)sizeof(float);   // 96KB
    cudaFuncSetAttribute(qg_ballquery_kernel,
                         cudaFuncAttributeMaxDynamicSharedMemorySize, dyn_smem);

    qg_ballquery_kernel<<<BATCH * 32, 1024, dyn_smem>>>(coords, queries, out);
    qg_gather_kernel<<<BATCH * 128, 256>>>(feats, temb, out);
}